// round 4
// baseline (speedup 1.0000x reference)
#include <cuda_runtime.h>
#include <cstdint>

// CenterLoss: BATCH=4096, FEAT_DIM=256, NUM_CLASSES=8192
#define BATCH       4096
#define FEAT_DIM    256
#define NUM_CLASSES 8192
#define NBLOCKS     64
#define NTHREADS    512          // 16 warps/block, 4 samples/warp, 1024 warps
#define SCALE       268435456.0  // 2^28 fixed-point scale

__device__ unsigned long long g_part[NBLOCKS];
__device__ unsigned int       g_count = 0u;

__global__ void __launch_bounds__(NTHREADS, 1) center_loss_fused(
    const float* __restrict__ x,
    const void*  __restrict__ labels_raw,
    const float* __restrict__ centers,
    float*       __restrict__ out)
{
    const int lane = threadIdx.x & 31;
    const int warp = threadIdx.x >> 5;               // 0..15
    const int gw   = blockIdx.x * 16 + warp;         // 0..1023
    // samples 4gw .. 4gw+3

    // Speculative i32-layout label quad: words 4gw..4gw+3.
    // In-bounds for BOTH layouts (i32: 4096 words, 4gw+3 <= 4095; i64: 8192).
    const int4 li = ((const int4*)labels_raw)[gw];

    // dtype probe: shared 8 odd words, L2-broadcast after first touch.
    int probe = (lane < 8) ? ((const int*)labels_raw)[2 * lane + 1] : 0;

    // x loads: 4 rows = 256 float4, 8 per lane. Independent of labels.
    const float4* xr = (const float4*)(x + (size_t)(4 * gw) * FEAT_DIM);
    float4 a[8];
#pragma unroll
    for (int i = 0; i < 8; i++) a[i] = xr[lane + 32 * i];

    const bool i64 = (__ballot_sync(0xFFFFFFFFu, probe != 0) == 0);

    int l0, l1, l2, l3;
    if (i64) {
        int4 p0 = ((const int4*)labels_raw)[2 * gw];
        int4 p1 = ((const int4*)labels_raw)[2 * gw + 1];
        l0 = p0.x; l1 = p0.z; l2 = p1.x; l3 = p1.z;
    } else {
        l0 = li.x; l1 = li.y; l2 = li.z; l3 = li.w;
    }

    // 8 independent gather loads, all issued before any consumption.
    const float4* c0 = (const float4*)(centers + (size_t)l0 * FEAT_DIM);
    const float4* c1 = (const float4*)(centers + (size_t)l1 * FEAT_DIM);
    const float4* c2 = (const float4*)(centers + (size_t)l2 * FEAT_DIM);
    const float4* c3 = (const float4*)(centers + (size_t)l3 * FEAT_DIM);
    float4 b[8];
    b[0] = c0[lane]; b[1] = c0[lane + 32];
    b[2] = c1[lane]; b[3] = c1[lane + 32];
    b[4] = c2[lane]; b[5] = c2[lane + 32];
    b[6] = c3[lane]; b[7] = c3[lane + 32];

    float acc[4] = {0.f, 0.f, 0.f, 0.f};
#pragma unroll
    for (int s = 0; s < 4; s++) {
#pragma unroll
        for (int h = 0; h < 2; h++) {
            float4 av = a[2 * s + h], bv = b[2 * s + h];
            float d;
            d = av.x - bv.x; acc[s] = fmaf(d, d, acc[s]);
            d = av.y - bv.y; acc[s] = fmaf(d, d, acc[s]);
            d = av.z - bv.z; acc[s] = fmaf(d, d, acc[s]);
            d = av.w - bv.w; acc[s] = fmaf(d, d, acc[s]);
        }
    }

#pragma unroll
    for (int o = 16; o > 0; o >>= 1) {
#pragma unroll
        for (int s = 0; s < 4; s++)
            acc[s] += __shfl_xor_sync(0xFFFFFFFFu, acc[s], o);
    }

    // Per-warp fixed-point partial (clamp per sample, faithful to reference).
    __shared__ unsigned long long sh[16];
    if (lane == 0) {
        unsigned long long w = 0ull;
#pragma unroll
        for (int s = 0; s < 4; s++) {
            float v = fminf(fmaxf(acc[s], 1e-12f), 1e12f);
            w += (unsigned long long)((double)v * SCALE);
        }
        sh[warp] = w;
    }
    __syncthreads();

    if (warp == 0) {
        unsigned long long w = (lane < 16) ? sh[lane] : 0ull;
#pragma unroll
        for (int o = 8; o > 0; o >>= 1)
            w += __shfl_xor_sync(0xFFFFFFFFu, w, o);

        unsigned int old = 0u;
        if (lane == 0) {
            g_part[blockIdx.x] = w;
            __threadfence();
            old = atomicAdd(&g_count, 1u);
        }
        old = __shfl_sync(0xFFFFFFFFu, old, 0);

        if (old == NBLOCKS - 1) {
            __threadfence();  // acquire: all g_part stores visible
            unsigned long long t = g_part[lane] + g_part[lane + 32];
#pragma unroll
            for (int o = 16; o > 0; o >>= 1)
                t += __shfl_xor_sync(0xFFFFFFFFu, t, o);
            if (lane == 0) {
                double loss = ((double)t / SCALE) / (double)BATCH
                            + (double)(NUM_CLASSES - 1) * 1e-12;
                out[0] = (float)loss;
                g_count = 0u;   // reset for next graph replay
            }
        }
    }
}

extern "C" void kernel_launch(void* const* d_in, const int* in_sizes, int n_in,
                              void* d_out, int out_size)
{
    const float* x       = (const float*)d_in[0];
    const void*  labels  = d_in[1];
    const float* centers = (const float*)d_in[2];
    float*       out     = (float*)d_out;
    (void)in_sizes; (void)n_in; (void)out_size;

    center_loss_fused<<<NBLOCKS, NTHREADS>>>(x, labels, centers, out);
}